// round 16
// baseline (speedup 1.0000x reference)
#include <cuda_runtime.h>
#include <cstdint>

#define LOG2E  1.4426950408889634f
#define LN2    0.6931471805599453f
#define SP     256            // padded extended-label stride (S <= 256)

__device__ __forceinline__ float ex2(float x) {
    float y; asm("ex2.approx.ftz.f32 %0, %1;" : "=f"(y) : "f"(x)); return y;
}
__device__ __forceinline__ float lg2(float x) {
    float y; asm("lg2.approx.f32 %0, %1;" : "=f"(y) : "f"(x)); return y;
}
// 2^d with clamp to [-127, 127]; d=-127 flushes to exact 0.
__device__ __forceinline__ float exp2c(int d) {
    d = d < -127 ? -127 : (d > 127 ? 127 : d);
    return __int_as_float((127 + d) << 23);
}

// scratch: p_ext [B][T][SP] (true softmax probs <= 1, zero-padded).
// +8192 pad floats so the DP's unguarded prefetch (up to 7 frames past len)
// can never read out of bounds; those values are never consumed.
#define MAX_LP (32 * 1000 * SP + 8192)
__device__ float g_lp[MAX_LP];
__device__ float g_costs[128];
__device__ int   g_done;          // self-resetting completion counter

// ---------------------------------------------------------------------------
// Kernel A: WARP-PER-ROW logsumexp + gather, MLP=8 batched float4 loads.
// Emits true probabilities p = 2^(x*log2e - lse2) <= 1 (pad positions 0.0).
// ---------------------------------------------------------------------------
__global__ void __launch_bounds__(256)
lse_gather_kernel(const float* __restrict__ act,
                  const int*   __restrict__ targets,
                  int T, int B, int C, int L, int S) {
    const int warp = threadIdx.x >> 5;
    const int lane = threadIdx.x & 31;
    const int r    = blockIdx.x * 8 + warp;       // row index = t*B + b
    if (r >= T * B) return;
    const int t = r / B;
    const int b = r - t * B;
    const float* row = act + (size_t)r * C;

    const int C4 = C >> 2;
    const float4* row4 = (const float4*)row;

    float acc0 = 0.f, acc1 = 0.f, acc2 = 0.f, acc3 = 0.f;
    int i = lane;
    for (; i + 224 < C4; i += 256) {
        float4 v0 = row4[i];
        float4 v1 = row4[i + 32];
        float4 v2 = row4[i + 64];
        float4 v3 = row4[i + 96];
        float4 v4 = row4[i + 128];
        float4 v5 = row4[i + 160];
        float4 v6 = row4[i + 192];
        float4 v7 = row4[i + 224];
        acc0 += (ex2(v0.x * LOG2E) + ex2(v0.y * LOG2E))
              + (ex2(v0.z * LOG2E) + ex2(v0.w * LOG2E));
        acc1 += (ex2(v1.x * LOG2E) + ex2(v1.y * LOG2E))
              + (ex2(v1.z * LOG2E) + ex2(v1.w * LOG2E));
        acc2 += (ex2(v2.x * LOG2E) + ex2(v2.y * LOG2E))
              + (ex2(v2.z * LOG2E) + ex2(v2.w * LOG2E));
        acc3 += (ex2(v3.x * LOG2E) + ex2(v3.y * LOG2E))
              + (ex2(v3.z * LOG2E) + ex2(v3.w * LOG2E));
        acc0 += (ex2(v4.x * LOG2E) + ex2(v4.y * LOG2E))
              + (ex2(v4.z * LOG2E) + ex2(v4.w * LOG2E));
        acc1 += (ex2(v5.x * LOG2E) + ex2(v5.y * LOG2E))
              + (ex2(v5.z * LOG2E) + ex2(v5.w * LOG2E));
        acc2 += (ex2(v6.x * LOG2E) + ex2(v6.y * LOG2E))
              + (ex2(v6.z * LOG2E) + ex2(v6.w * LOG2E));
        acc3 += (ex2(v7.x * LOG2E) + ex2(v7.y * LOG2E))
              + (ex2(v7.z * LOG2E) + ex2(v7.w * LOG2E));
    }
    for (; i + 96 < C4; i += 128) {
        float4 v0 = row4[i];
        float4 v1 = row4[i + 32];
        float4 v2 = row4[i + 64];
        float4 v3 = row4[i + 96];
        acc0 += (ex2(v0.x * LOG2E) + ex2(v0.y * LOG2E))
              + (ex2(v0.z * LOG2E) + ex2(v0.w * LOG2E));
        acc1 += (ex2(v1.x * LOG2E) + ex2(v1.y * LOG2E))
              + (ex2(v1.z * LOG2E) + ex2(v1.w * LOG2E));
        acc2 += (ex2(v2.x * LOG2E) + ex2(v2.y * LOG2E))
              + (ex2(v2.z * LOG2E) + ex2(v2.w * LOG2E));
        acc3 += (ex2(v3.x * LOG2E) + ex2(v3.y * LOG2E))
              + (ex2(v3.z * LOG2E) + ex2(v3.w * LOG2E));
    }
    for (; i < C4; i += 32) {
        float4 v = row4[i];
        acc0 += (ex2(v.x * LOG2E) + ex2(v.y * LOG2E))
              + (ex2(v.z * LOG2E) + ex2(v.w * LOG2E));
    }
    for (int j = (C4 << 2) + lane; j < C; j += 32)
        acc1 += ex2(row[j] * LOG2E);

    float sum = (acc0 + acc1) + (acc2 + acc3);
    #pragma unroll
    for (int o = 16; o; o >>= 1) sum += __shfl_xor_sync(~0u, sum, o);
    const float lse2 = lg2(sum);                  // logsumexp, log2 domain

    float* outp = g_lp + ((size_t)b * T + t) * SP;
    const int* tg = targets + b * L;
    #pragma unroll
    for (int k = 0; k < SP / 32; k++) {
        const int s = lane + 32 * k;
        float val = 0.f;
        if (s < S) {
            int col = (s & 1) ? tg[s >> 1] : 0;
            val = ex2(fmaf(row[col], LOG2E, -lse2));
        }
        outp[s] = val;
    }
}

// ---------------------------------------------------------------------------
// Kernel B: alpha recursion, LINEAR domain, per-lane block floating point.
// One warp per utterance, 8 alphas per lane, own exponent E per lane.
// STEP computes n7 + its shfl FIRST (hides SHFL latency behind n0..n6).
// RENORM (every 4 steps) uses TWO PARALLEL shfls of a packed (Et<<1|actv)
// word; the left lane's post-adoption exponent En_p is recomputed locally
// as an exact replica (same inputs -> same result), and an Eold_p shadow
// register (updated to En_p each renorm) supplies the left lane's previous
// base for the in-flight h rescale. Algebraically identical to the round-12
// scheme (sc = 2^(E-En) collapses self-norm+rebase; inactive lanes multiply
// zeros so their sc value is irrelevant as long as finite).
// In-place ring of 4 frames (<=8 outstanding LDGs, fits 6 SB slots) with
// pointer-increment addressing (constant LDG offsets).
// Last-finishing block computes the final scalar inline (no extra launch).
// ---------------------------------------------------------------------------
__global__ void __launch_bounds__(32, 1)
ctc_dp_kernel(const int* __restrict__ targets,
              const int* __restrict__ in_len,
              const int* __restrict__ tg_len,
              int T, int B, int L, int S,
              float* __restrict__ out) {
    const int b    = blockIdx.x;
    const int lane = threadIdx.x;
    const int s0   = lane << 3;

    float skm1, skm3, skm5, skm7;
    {
        const int* tg = targets + b * L;
        #define SKF(sv, dst) { int li = (sv) >> 1;                         \
            if (li >= L) dst = 0.f;                                        \
            else if (li == 0) dst = 1.f;                                   \
            else dst = (tg[li] != tg[li - 1]) ? 1.f : 0.f; }
        SKF(s0 + 1, skm1); SKF(s0 + 3, skm3); SKF(s0 + 5, skm5); SKF(s0 + 7, skm7);
        #undef SKF
    }

    const int len    = in_len[b];
    const int s_last = 2 * tg_len[b];
    const float* base = g_lp + (size_t)b * T * SP + s0;

    // t = 0 init (linear): only s = 0, 1 live
    float a[8];
    {
        const float4* p = (const float4*)base;
        float4 q0 = p[0];
        a[0] = (s0 == 0) ? q0.x : 0.f;
        a[1] = (lane == 0) ? q0.y : 0.f;
        #pragma unroll
        for (int k = 2; k < 8; k++) a[k] = 0.f;
    }
    float h = 0.f, hscale = 1.f;
    int   E = 0;          // own exponent base
    int   Eold_p = 0;     // shadow of LEFT lane's exponent base (exact replica)

    #define STEP(L0, L1) do {                                              \
        float n7 = fmaf(a[5], skm7, a[7] + a[6])  * (L1).w;                \
        float nh = __shfl_up_sync(0xffffffffu, n7, 1);                     \
        float hv = h * hscale;                                             \
        float n0 = (a[0] + hv)                    * (L0).x;                \
        float n1 = fmaf(hv,   skm1, a[1] + a[0])  * (L0).y;                \
        float n2 = (a[2] + a[1])                  * (L0).z;                \
        float n3 = fmaf(a[1], skm3, a[3] + a[2])  * (L0).w;                \
        float n4 = (a[4] + a[3])                  * (L1).x;                \
        float n5 = fmaf(a[3], skm5, a[5] + a[4])  * (L1).y;                \
        float n6 = (a[6] + a[5])                  * (L1).z;                \
        a[0]=n0; a[1]=n1; a[2]=n2; a[3]=n3;                                \
        a[4]=n4; a[5]=n5; a[6]=n6; a[7]=n7;                                \
        h = (lane == 0) ? 0.f : nh;                                        \
    } while (0)

    #define RENORM() do {                                                  \
        float m = fmaxf(fmaxf(fmaxf(a[0],a[1]), fmaxf(a[2],a[3])),        \
                        fmaxf(fmaxf(a[4],a[5]), fmaxf(a[6],a[7])));        \
        int eb = (__float_as_int(m) >> 23) & 255;                          \
        int actv = (eb != 0) ? 1 : 0;                                      \
        int Et = E + (actv ? (eb - 127) : 0);                              \
        int w  = (Et << 1) | actv;                                         \
        int w1 = __shfl_up_sync(0xffffffffu, w, 1);                        \
        int w2 = __shfl_up_sync(0xffffffffu, w, 2);                        \
        if (lane == 0) w1 = w;                                             \
        if (lane <= 1) w2 = w1;                                            \
        int Et_p  = w1 >> 1; int actv_p = w1 & 1;                          \
        int Et_pp = w2 >> 1;                                               \
        int En   = actv   ? (Et   > Et_p  ? Et   : Et_p ) : Et_p;          \
        int En_p = actv_p ? (Et_p > Et_pp ? Et_p : Et_pp) : Et_pp;         \
        float sc = exp2c(E - En);                                          \
        _Pragma("unroll")                                                  \
        for (int k = 0; k < 8; k++) a[k] *= sc;                            \
        h *= exp2c(Eold_p - En_p);        /* h into left's NEW units */    \
        int d2 = En_p - En;                                                \
        d2 = d2 > 60 ? 60 : d2;                                            \
        hscale = exp2c(d2);                                                \
        if (lane == 0) hscale = 1.f;                                       \
        E = En; Eold_p = En_p;                                             \
    } while (0)

    #define LDQ(da, db, ptr) { const float4* _p = (const float4*)(ptr);    \
        da = _p[0]; db = _p[1]; }

    // ring preload: slot j holds frame 1+j
    float4 ra[4], rb[4];
    {
        const float* q0 = base + SP;
        LDQ(ra[0], rb[0], q0);
        LDQ(ra[1], rb[1], q0 + SP);
        LDQ(ra[2], rb[2], q0 + 2 * SP);
        LDQ(ra[3], rb[3], q0 + 3 * SP);
    }
    const float* q = base + 5 * SP;     // reload source for first group

    int t = 1;
    for (; t + 3 <= len - 1; t += 4) {
        STEP(ra[0], rb[0]); LDQ(ra[0], rb[0], q);
        STEP(ra[1], rb[1]); LDQ(ra[1], rb[1], q + SP);
        STEP(ra[2], rb[2]); LDQ(ra[2], rb[2], q + 2 * SP);
        STEP(ra[3], rb[3]); LDQ(ra[3], rb[3], q + 3 * SP);
        RENORM();
        q += 4 * SP;
    }
    // tail: slot j holds frame t+j; <= 3 steps remain
    {
        int rem = (len - 1) - t + 1;         // 0..3
        if (rem > 0) { STEP(ra[0], rb[0]); }
        if (rem > 1) { STEP(ra[1], rb[1]); }
        if (rem > 2) { STEP(ra[2], rb[2]); }
    }
    RENORM();                                // normalize before capture

    // capture alpha_{len-1}[s_last], [s_last-1] (+ lane exponents)
    const int sb = s_last, sl = s_last - 1;
    float vb = a[0], vl = a[0];
    #pragma unroll
    for (int k = 1; k < 8; k++) {
        vb = ((sb & 7) == k) ? a[k] : vb;
        vl = ((sl & 7) == k) ? a[k] : vl;
    }
    float ab = __shfl_sync(0xffffffffu, vb, sb >> 3);
    float al = __shfl_sync(0xffffffffu, vl, sl >> 3);
    int   Eb = __shfl_sync(0xffffffffu, E,  sb >> 3);
    int   El = __shfl_sync(0xffffffffu, E,  sl >> 3);

    if (lane == 0) {
        float c2b = lg2(ab) + (float)Eb;
        float c2l = lg2(al) + (float)El;
        float hi = fmaxf(c2b, c2l), lo = fminf(c2b, c2l);
        float dd = fmaxf(lo - hi, -126.f);
        float c2 = hi + lg2(1.f + ex2(dd));
        g_costs[b] = -c2 * LN2;
    }

    // ---- inline finalize: last block to finish reduces g_costs ----
    __threadfence();
    int done = 0;
    if (lane == 0) done = (atomicAdd(&g_done, 1) == B - 1) ? 1 : 0;
    done = __shfl_sync(0xffffffffu, done, 0);
    if (done) {
        __threadfence();
        float cs = 0.f, ts = 0.f;
        if (lane < B) {
            cs = g_costs[lane];
            ts = (float)tg_len[lane];
        }
        #pragma unroll
        for (int o = 16; o; o >>= 1) {
            cs += __shfl_xor_sync(~0u, cs, o);
            ts += __shfl_xor_sync(~0u, ts, o);
        }
        if (lane == 0) {
            out[0] = cs / (float)B / ts;
            g_done = 0;                      // self-reset for graph replays
            __threadfence();
        }
    }
    #undef STEP
    #undef RENORM
    #undef LDQ
}

extern "C" void kernel_launch(void* const* d_in, const int* in_sizes, int n_in,
                              void* d_out, int out_size) {
    const float* act     = (const float*)d_in[0];   // [T,B,C]
    const int*   targets = (const int*)d_in[1];     // [B*L]
    const int*   in_len  = (const int*)d_in[2];     // [B]
    const int*   tg_len  = (const int*)d_in[3];     // [B]

    const int B = in_sizes[2];
    const int L = in_sizes[1] / B;
    const int T = 1000;
    const int C = in_sizes[0] / (B * T);
    const int S = 2 * L + 1;

    const int rows = T * B;
    lse_gather_kernel<<<(rows + 7) / 8, 256>>>(act, targets, T, B, C, L, S);
    ctc_dp_kernel<<<B, 32>>>(targets, in_len, tg_len, T, B, L, S, (float*)d_out);
}

// round 17
// speedup vs baseline: 1.3735x; 1.3735x over previous
#include <cuda_runtime.h>
#include <cstdint>

#define LOG2E  1.4426950408889634f
#define LN2    0.6931471805599453f
#define SP     256            // padded extended-label stride (S <= 256)

__device__ __forceinline__ float ex2(float x) {
    float y; asm("ex2.approx.ftz.f32 %0, %1;" : "=f"(y) : "f"(x)); return y;
}
__device__ __forceinline__ float lg2(float x) {
    float y; asm("lg2.approx.f32 %0, %1;" : "=f"(y) : "f"(x)); return y;
}
// 2^d with clamp to [-127, 127]; d=-127 flushes to exact 0.
__device__ __forceinline__ float exp2c(int d) {
    d = d < -127 ? -127 : (d > 127 ? 127 : d);
    return __int_as_float((127 + d) << 23);
}

// scratch: p_ext [B][T][SP] (true softmax probs <= 1, zero-padded).
// +8192 pad floats so the DP's unguarded distance-8 prefetch (up to 15
// frames past len) can never read out of bounds; values never consumed.
#define MAX_LP (32 * 1000 * SP + 8192)
__device__ float g_lp[MAX_LP];
__device__ float g_costs[128];
__device__ int   g_done;          // self-resetting completion counter

// ---------------------------------------------------------------------------
// Kernel A: WARP-PER-ROW logsumexp + gather, MLP=8 batched float4 loads.
// Emits true probabilities p = 2^(x*log2e - lse2) <= 1 (pad positions 0.0).
// ---------------------------------------------------------------------------
__global__ void __launch_bounds__(256)
lse_gather_kernel(const float* __restrict__ act,
                  const int*   __restrict__ targets,
                  int T, int B, int C, int L, int S) {
    const int warp = threadIdx.x >> 5;
    const int lane = threadIdx.x & 31;
    const int r    = blockIdx.x * 8 + warp;       // row index = t*B + b
    if (r >= T * B) return;
    const int t = r / B;
    const int b = r - t * B;
    const float* row = act + (size_t)r * C;

    const int C4 = C >> 2;
    const float4* row4 = (const float4*)row;

    float acc0 = 0.f, acc1 = 0.f, acc2 = 0.f, acc3 = 0.f;
    int i = lane;
    for (; i + 224 < C4; i += 256) {
        float4 v0 = row4[i];
        float4 v1 = row4[i + 32];
        float4 v2 = row4[i + 64];
        float4 v3 = row4[i + 96];
        float4 v4 = row4[i + 128];
        float4 v5 = row4[i + 160];
        float4 v6 = row4[i + 192];
        float4 v7 = row4[i + 224];
        acc0 += (ex2(v0.x * LOG2E) + ex2(v0.y * LOG2E))
              + (ex2(v0.z * LOG2E) + ex2(v0.w * LOG2E));
        acc1 += (ex2(v1.x * LOG2E) + ex2(v1.y * LOG2E))
              + (ex2(v1.z * LOG2E) + ex2(v1.w * LOG2E));
        acc2 += (ex2(v2.x * LOG2E) + ex2(v2.y * LOG2E))
              + (ex2(v2.z * LOG2E) + ex2(v2.w * LOG2E));
        acc3 += (ex2(v3.x * LOG2E) + ex2(v3.y * LOG2E))
              + (ex2(v3.z * LOG2E) + ex2(v3.w * LOG2E));
        acc0 += (ex2(v4.x * LOG2E) + ex2(v4.y * LOG2E))
              + (ex2(v4.z * LOG2E) + ex2(v4.w * LOG2E));
        acc1 += (ex2(v5.x * LOG2E) + ex2(v5.y * LOG2E))
              + (ex2(v5.z * LOG2E) + ex2(v5.w * LOG2E));
        acc2 += (ex2(v6.x * LOG2E) + ex2(v6.y * LOG2E))
              + (ex2(v6.z * LOG2E) + ex2(v6.w * LOG2E));
        acc3 += (ex2(v7.x * LOG2E) + ex2(v7.y * LOG2E))
              + (ex2(v7.z * LOG2E) + ex2(v7.w * LOG2E));
    }
    for (; i + 96 < C4; i += 128) {
        float4 v0 = row4[i];
        float4 v1 = row4[i + 32];
        float4 v2 = row4[i + 64];
        float4 v3 = row4[i + 96];
        acc0 += (ex2(v0.x * LOG2E) + ex2(v0.y * LOG2E))
              + (ex2(v0.z * LOG2E) + ex2(v0.w * LOG2E));
        acc1 += (ex2(v1.x * LOG2E) + ex2(v1.y * LOG2E))
              + (ex2(v1.z * LOG2E) + ex2(v1.w * LOG2E));
        acc2 += (ex2(v2.x * LOG2E) + ex2(v2.y * LOG2E))
              + (ex2(v2.z * LOG2E) + ex2(v2.w * LOG2E));
        acc3 += (ex2(v3.x * LOG2E) + ex2(v3.y * LOG2E))
              + (ex2(v3.z * LOG2E) + ex2(v3.w * LOG2E));
    }
    for (; i < C4; i += 32) {
        float4 v = row4[i];
        acc0 += (ex2(v.x * LOG2E) + ex2(v.y * LOG2E))
              + (ex2(v.z * LOG2E) + ex2(v.w * LOG2E));
    }
    for (int j = (C4 << 2) + lane; j < C; j += 32)
        acc1 += ex2(row[j] * LOG2E);

    float sum = (acc0 + acc1) + (acc2 + acc3);
    #pragma unroll
    for (int o = 16; o; o >>= 1) sum += __shfl_xor_sync(~0u, sum, o);
    const float lse2 = lg2(sum);                  // logsumexp, log2 domain

    float* outp = g_lp + ((size_t)b * T + t) * SP;
    const int* tg = targets + b * L;
    #pragma unroll
    for (int k = 0; k < SP / 32; k++) {
        const int s = lane + 32 * k;
        float val = 0.f;
        if (s < S) {
            int col = (s & 1) ? tg[s >> 1] : 0;
            val = ex2(fmaf(row[col], LOG2E, -lse2));
        }
        outp[s] = val;
    }
}

// ---------------------------------------------------------------------------
// Kernel B: alpha recursion, LINEAR domain, per-lane block floating point.
// One warp per utterance, 8 alphas per lane, own exponent E per lane.
// Ring: distance-8 prefetch into SEPARATE registers with copies after use
// (the r12 structure that measured fastest; in-place reload variants create
// WAR coupling and exposed scoreboard waits).
// STEP computes n7 + its shfl FIRST (hides SHFL latency behind n0..n6).
// RENORM (every 4 steps) uses TWO PARALLEL shfls of a packed (Et<<1|actv)
// word; the left lane's post-adoption exponent En_p is recomputed locally
// as an exact replica, with an Eold_p shadow for the in-flight h rescale.
// Last-finishing block computes the final scalar inline (no extra launch).
// ---------------------------------------------------------------------------
__global__ void __launch_bounds__(32, 1)
ctc_dp_kernel(const int* __restrict__ targets,
              const int* __restrict__ in_len,
              const int* __restrict__ tg_len,
              int T, int B, int L, int S,
              float* __restrict__ out) {
    const int b    = blockIdx.x;
    const int lane = threadIdx.x;
    const int s0   = lane << 3;

    float skm1, skm3, skm5, skm7;
    {
        const int* tg = targets + b * L;
        #define SKF(sv, dst) { int li = (sv) >> 1;                         \
            if (li >= L) dst = 0.f;                                        \
            else if (li == 0) dst = 1.f;                                   \
            else dst = (tg[li] != tg[li - 1]) ? 1.f : 0.f; }
        SKF(s0 + 1, skm1); SKF(s0 + 3, skm3); SKF(s0 + 5, skm5); SKF(s0 + 7, skm7);
        #undef SKF
    }

    const int len    = in_len[b];
    const int s_last = 2 * tg_len[b];
    const float* base = g_lp + (size_t)b * T * SP + s0;

    // t = 0 init (linear): only s = 0, 1 live
    float a[8];
    {
        const float4* p = (const float4*)base;
        float4 q0 = p[0];
        a[0] = (s0 == 0) ? q0.x : 0.f;
        a[1] = (lane == 0) ? q0.y : 0.f;
        #pragma unroll
        for (int k = 2; k < 8; k++) a[k] = 0.f;
    }
    float h = 0.f, hscale = 1.f;
    int   E = 0;          // own exponent base
    int   Eold_p = 0;     // shadow of LEFT lane's exponent base (exact replica)

    #define STEP(L0, L1) do {                                              \
        float n7 = fmaf(a[5], skm7, a[7] + a[6])  * (L1).w;                \
        float nh = __shfl_up_sync(0xffffffffu, n7, 1);                     \
        float hv = h * hscale;                                             \
        float n0 = (a[0] + hv)                    * (L0).x;                \
        float n1 = fmaf(hv,   skm1, a[1] + a[0])  * (L0).y;                \
        float n2 = (a[2] + a[1])                  * (L0).z;                \
        float n3 = fmaf(a[1], skm3, a[3] + a[2])  * (L0).w;                \
        float n4 = (a[4] + a[3])                  * (L1).x;                \
        float n5 = fmaf(a[3], skm5, a[5] + a[4])  * (L1).y;                \
        float n6 = (a[6] + a[5])                  * (L1).z;                \
        a[0]=n0; a[1]=n1; a[2]=n2; a[3]=n3;                                \
        a[4]=n4; a[5]=n5; a[6]=n6; a[7]=n7;                                \
        h = (lane == 0) ? 0.f : nh;                                        \
    } while (0)

    #define RENORM() do {                                                  \
        float m = fmaxf(fmaxf(fmaxf(a[0],a[1]), fmaxf(a[2],a[3])),        \
                        fmaxf(fmaxf(a[4],a[5]), fmaxf(a[6],a[7])));        \
        int eb = (__float_as_int(m) >> 23) & 255;                          \
        int actv = (eb != 0) ? 1 : 0;                                      \
        int Et = E + (actv ? (eb - 127) : 0);                              \
        int w  = (Et << 1) | actv;                                         \
        int w1 = __shfl_up_sync(0xffffffffu, w, 1);                        \
        int w2 = __shfl_up_sync(0xffffffffu, w, 2);                        \
        if (lane == 0) w1 = w;                                             \
        if (lane <= 1) w2 = w1;                                            \
        int Et_p  = w1 >> 1; int actv_p = w1 & 1;                          \
        int Et_pp = w2 >> 1;                                               \
        int En   = actv   ? (Et   > Et_p  ? Et   : Et_p ) : Et_p;          \
        int En_p = actv_p ? (Et_p > Et_pp ? Et_p : Et_pp) : Et_pp;         \
        float sc = exp2c(E - En);                                          \
        _Pragma("unroll")                                                  \
        for (int k = 0; k < 8; k++) a[k] *= sc;                            \
        h *= exp2c(Eold_p - En_p);        /* h into left's NEW units */    \
        int d2 = En_p - En;                                                \
        d2 = d2 > 60 ? 60 : d2;                                            \
        hscale = exp2c(d2);                                                \
        if (lane == 0) hscale = 1.f;                                       \
        E = En; Eold_p = En_p;                                             \
    } while (0)

    #define LDQ(da, db, ptr) { const float4* _p = (const float4*)(ptr);    \
        da = _p[0]; db = _p[1]; }

    // ring preload: slot j holds frame 1+j (distance 8)
    float4 ra[8], rb[8];
    #pragma unroll
    for (int j = 0; j < 8; j++) LDQ(ra[j], rb[j], base + (size_t)(1 + j) * SP);

    int t = 1;
    for (; t + 7 <= len - 1; t += 8) {
        float4 pa[8], pb[8];
        #pragma unroll
        for (int j = 0; j < 8; j++) {
            LDQ(pa[j], pb[j], base + (size_t)(t + 8 + j) * SP);
            STEP(ra[j], rb[j]);
            if (j == 3 || j == 7) RENORM();
        }
        #pragma unroll
        for (int j = 0; j < 8; j++) { ra[j] = pa[j]; rb[j] = pb[j]; }
    }
    // tail: slot j holds frame t+j; <= 7 steps remain
    {
        int rem = len - t;                   // steps remaining (0..7)
        if (rem > 0) { STEP(ra[0], rb[0]); }
        if (rem > 1) { STEP(ra[1], rb[1]); }
        if (rem > 2) { STEP(ra[2], rb[2]); }
        if (rem > 3) { STEP(ra[3], rb[3]); }
        if (rem > 4) { STEP(ra[4], rb[4]); }
        if (rem > 5) { STEP(ra[5], rb[5]); }
        if (rem > 6) { STEP(ra[6], rb[6]); }
    }
    RENORM();                                // normalize before capture

    // capture alpha_{len-1}[s_last], [s_last-1] (+ lane exponents)
    const int sb = s_last, sl = s_last - 1;
    float vb = a[0], vl = a[0];
    #pragma unroll
    for (int k = 1; k < 8; k++) {
        vb = ((sb & 7) == k) ? a[k] : vb;
        vl = ((sl & 7) == k) ? a[k] : vl;
    }
    float ab = __shfl_sync(0xffffffffu, vb, sb >> 3);
    float al = __shfl_sync(0xffffffffu, vl, sl >> 3);
    int   Eb = __shfl_sync(0xffffffffu, E,  sb >> 3);
    int   El = __shfl_sync(0xffffffffu, E,  sl >> 3);

    if (lane == 0) {
        float c2b = lg2(ab) + (float)Eb;
        float c2l = lg2(al) + (float)El;
        float hi = fmaxf(c2b, c2l), lo = fminf(c2b, c2l);
        float dd = fmaxf(lo - hi, -126.f);
        float c2 = hi + lg2(1.f + ex2(dd));
        g_costs[b] = -c2 * LN2;
    }

    // ---- inline finalize: last block to finish reduces g_costs ----
    __threadfence();
    int done = 0;
    if (lane == 0) done = (atomicAdd(&g_done, 1) == B - 1) ? 1 : 0;
    done = __shfl_sync(0xffffffffu, done, 0);
    if (done) {
        __threadfence();
        float cs = 0.f, ts = 0.f;
        if (lane < B) {
            cs = g_costs[lane];
            ts = (float)tg_len[lane];
        }
        #pragma unroll
        for (int o = 16; o; o >>= 1) {
            cs += __shfl_xor_sync(~0u, cs, o);
            ts += __shfl_xor_sync(~0u, ts, o);
        }
        if (lane == 0) {
            out[0] = cs / (float)B / ts;
            g_done = 0;                      // self-reset for graph replays
            __threadfence();
        }
    }
    #undef STEP
    #undef RENORM
    #undef LDQ
}

extern "C" void kernel_launch(void* const* d_in, const int* in_sizes, int n_in,
                              void* d_out, int out_size) {
    const float* act     = (const float*)d_in[0];   // [T,B,C]
    const int*   targets = (const int*)d_in[1];     // [B*L]
    const int*   in_len  = (const int*)d_in[2];     // [B]
    const int*   tg_len  = (const int*)d_in[3];     // [B]

    const int B = in_sizes[2];
    const int L = in_sizes[1] / B;
    const int T = 1000;
    const int C = in_sizes[0] / (B * T);
    const int S = 2 * L + 1;

    const int rows = T * B;
    lse_gather_kernel<<<(rows + 7) / 8, 256>>>(act, targets, T, B, C, L, S);
    ctc_dp_kernel<<<B, 32>>>(targets, in_len, tg_len, T, B, L, S, (float*)d_out);
}